// round 2
// baseline (speedup 1.0000x reference)
#include <cuda_runtime.h>
#include <cstdint>

#define NV 10000
#define NC 100000
#define B  256
#define GRID_MAIN 1480
#define CPB ((NC + GRID_MAIN - 1) / GRID_MAIN)   // clauses per block = 68

// Packed literal: (var_index << 1) | neg_flag. 1.2 MB, L2-resident.
__device__ unsigned int g_packed[NC * 3];
__device__ int g_is64;   // 1 if literal arrays are int64, 0 if int32

// Detect dtype of lit_idx by inspecting odd 32-bit words.
// int64 data (values < 2^31, >= 0): odd words are high words == 0, always.
// int32 data: odd words are random indices in [0, NV) -> all-zero is ~impossible.
__global__ void detect_k(const unsigned int* __restrict__ lit_idx_raw) {
    unsigned int acc = 0;
    for (int i = 0; i < 128; ++i) acc |= lit_idx_raw[2 * i + 1];
    g_is64 = (acc == 0) ? 1 : 0;
}

__global__ void pack_k(const unsigned int* __restrict__ idx_raw,
                       const unsigned int* __restrict__ neg_raw) {
    int i = blockIdx.x * blockDim.x + threadIdx.x;
    if (i < NC * 3) {
        int stride = g_is64 ? 2 : 1;          // int64 -> low word at even offset
        unsigned int v = idx_raw[i * stride];
        unsigned int n = neg_raw[i * stride] & 1u;
        if (v >= NV) v = NV - 1;              // defensive clamp: no OOB ever
        g_packed[i] = (v << 1) | n;
    }
}

__global__ void init_k(unsigned int* __restrict__ out) {
    out[threadIdx.x] = 0x7F800000u;   // +inf bit pattern
}

// 128 threads/block; thread t owns batch elements 2t and 2t+1 (float2 loads).
// Each block scans a contiguous chunk of clauses, keeps a running min,
// then folds into d_out with atomicMin on uint bits (valid: all values >= 0).
__global__ void __launch_bounds__(128)
cnf_k(const float* __restrict__ input, unsigned int* __restrict__ out) {
    const int t    = threadIdx.x;
    const int cbeg = blockIdx.x * CPB;
    const int cend = min(cbeg + CPB, NC);

    float m0 = __int_as_float(0x7F800000);
    float m1 = m0;
    const float2* __restrict__ in2 = (const float2*)input;

    #pragma unroll 4
    for (int c = cbeg; c < cend; ++c) {
        unsigned int w0 = __ldg(&g_packed[c * 3 + 0]);
        unsigned int w1 = __ldg(&g_packed[c * 3 + 1]);
        unsigned int w2 = __ldg(&g_packed[c * 3 + 2]);

        float2 x0 = __ldg(&in2[(w0 >> 1) * (B / 2) + t]);
        float2 x1 = __ldg(&in2[(w1 >> 1) * (B / 2) + t]);
        float2 x2 = __ldg(&in2[(w2 >> 1) * (B / 2) + t]);

        float n0 = (float)(w0 & 1u);
        float n1 = (float)(w1 & 1u);
        float n2 = (float)(w2 & 1u);

        // neg ? 1-x : x  ==  |neg_f - x|  for x in [0,1)
        float c0 = fmaxf(fmaxf(fabsf(n0 - x0.x), fabsf(n1 - x1.x)), fabsf(n2 - x2.x));
        float c1 = fmaxf(fmaxf(fabsf(n0 - x0.y), fabsf(n1 - x1.y)), fabsf(n2 - x2.y));

        m0 = fminf(m0, c0);
        m1 = fminf(m1, c1);
    }

    // uint bit order == float order for non-negative floats
    atomicMin(&out[2 * t + 0], __float_as_uint(m0));
    atomicMin(&out[2 * t + 1], __float_as_uint(m1));
}

extern "C" void kernel_launch(void* const* d_in, const int* in_sizes, int n_in,
                              void* d_out, int out_size) {
    const float*        input   = (const float*)d_in[0];
    const unsigned int* idx_raw = (const unsigned int*)d_in[1];
    const unsigned int* neg_raw = (const unsigned int*)d_in[2];
    unsigned int*       out     = (unsigned int*)d_out;

    detect_k<<<1, 1>>>(idx_raw);
    pack_k<<<(NC * 3 + 255) / 256, 256>>>(idx_raw, neg_raw);
    init_k<<<1, B>>>(out);
    cnf_k<<<GRID_MAIN, 128>>>(input, out);
}